// round 3
// baseline (speedup 1.0000x reference)
#include <cuda_runtime.h>

// ---------------------------------------------------------------------------
// HybridSAGEClassifier on GB300 — fp32 baseline.
//   CSR build (hist/scan/scatter) once, then per layer:
//     A = X@Wl ; H = X@Wr + b ; H += SpMM(A)/deg ; BN stats ; BN+ReLU
//   then fusion MLP.
// NOTE: edge_index is int32 on the wire (JAX x64-disabled downcasts the
// declared int64). Reading it as int64 was the cause of the err-717 crash
// in rounds 1-2 (wild atomics into the shared aperture).
// ---------------------------------------------------------------------------

static constexpr int N_NODES = 100000;
static constexpr int N_EDGES = 1200000;

// -------- device-global scratch (no allocation allowed) --------------------
__device__ __align__(128) int   g_deg[N_NODES];
__device__ __align__(128) int   g_rowptr[N_NODES + 1];
__device__ __align__(128) int   g_cursor[N_NODES];
__device__ __align__(128) int   g_col[N_EDGES];
__device__ __align__(128) float g_inv[N_NODES];
__device__ __align__(128) float g_bufA[(size_t)N_NODES * 64];
__device__ __align__(128) float g_buf0[(size_t)N_NODES * 64];
__device__ __align__(128) float g_buf1[(size_t)N_NODES * 64];
__device__ __align__(128) float g_sum[64];
__device__ __align__(128) float g_sumsq[64];
__device__ __align__(128) float g_scale[64];
__device__ __align__(128) float g_shift[64];

// buffer selector: 0 = g_bufA, 1 = g_buf0, 2 = g_buf1
__device__ __forceinline__ float* getbuf(int s) {
    return (s == 0) ? g_bufA : (s == 1) ? g_buf0 : g_buf1;
}

__device__ __forceinline__ int clampN(int v) {
    return (v < 0) ? 0 : (v >= N_NODES ? N_NODES - 1 : v);
}

// -------- CSR build --------------------------------------------------------
__global__ void k_zero_deg() {
    int i = blockIdx.x * blockDim.x + threadIdx.x;
    if (i < N_NODES) g_deg[i] = 0;
}

__global__ void k_zero_stats() {
    int i = threadIdx.x;
    if (i < 64) { g_sum[i] = 0.f; g_sumsq[i] = 0.f; }
}

__global__ void k_hist(const int* __restrict__ ei) {
    int e = blockIdx.x * blockDim.x + threadIdx.x;
    if (e < N_EDGES) atomicAdd(&g_deg[clampN(ei[N_EDGES + e])], 1);
}

__global__ void k_scan() {
    __shared__ int sh[1024];
    int tid = threadIdx.x;
    const int C = (N_NODES + 1023) / 1024;
    int beg = tid * C;
    int end = beg + C;
    if (beg > N_NODES) beg = N_NODES;
    if (end > N_NODES) end = N_NODES;
    int s = 0;
    for (int i = beg; i < end; i++) s += g_deg[i];
    sh[tid] = s;
    __syncthreads();
    for (int off = 1; off < 1024; off <<= 1) {
        int add = (tid >= off) ? sh[tid - off] : 0;
        __syncthreads();
        sh[tid] += add;
        __syncthreads();
    }
    int base = (tid == 0) ? 0 : sh[tid - 1];
    for (int i = beg; i < end; i++) {
        g_rowptr[i] = base;
        g_cursor[i] = base;
        int d = g_deg[i];
        g_inv[i] = 1.0f / (float)(d > 0 ? d : 1);
        base += d;
    }
    if (tid == 0) g_rowptr[N_NODES] = N_EDGES;
}

__global__ void k_scatter(const int* __restrict__ ei) {
    int e = blockIdx.x * blockDim.x + threadIdx.x;
    if (e < N_EDGES) {
        int d = clampN(ei[N_EDGES + e]);
        int p = atomicAdd(&g_cursor[d], 1);
        g_col[p] = clampN(ei[e]);
    }
}

// -------- GEMM: Out[N,64] = X[N,D] @ W[D,64] (+ bias) -----------------------
// 64x64 tile, 128 threads, 4x8 microtile per thread. FMA-bound by design.
// xsel < 0 -> use external pointer Xext; else internal buffer. Out = getbuf(osel).
template <int D>
__global__ __launch_bounds__(128) void k_gemm(const float* __restrict__ Xext,
                                              int xsel,
                                              const float* __restrict__ W,
                                              const float* __restrict__ bias,
                                              int osel) {
    const float* __restrict__ X = (xsel < 0) ? Xext : getbuf(xsel);
    float* __restrict__ Out = getbuf(osel);

    __shared__ float Xs[32][65];   // [k][row], padded
    __shared__ float Ws[32][64];   // [k][col]
    const int tid  = threadIdx.x;
    const int row0 = blockIdx.x * 64;
    const int ty4  = (tid >> 3) * 4;   // row group of 4
    const int tx8  = (tid & 7) * 8;    // col group of 8

    float acc[4][8];
#pragma unroll
    for (int i = 0; i < 4; i++)
#pragma unroll
        for (int j = 0; j < 8; j++) acc[i][j] = 0.f;

    for (int k0 = 0; k0 < D; k0 += 32) {
        // X tile: 64 rows x 32 k, float4 global loads
#pragma unroll
        for (int i = 0; i < 4; i++) {
            int idx = tid + i * 128;          // 0..511
            int r   = idx >> 3;               // 0..63
            int kg  = idx & 7;                // 0..7
            int rr  = row0 + r;
            if (rr >= N_NODES) rr = N_NODES - 1;
            float4 v = *(const float4*)(X + (size_t)rr * D + k0 + kg * 4);
            Xs[kg * 4 + 0][r] = v.x;
            Xs[kg * 4 + 1][r] = v.y;
            Xs[kg * 4 + 2][r] = v.z;
            Xs[kg * 4 + 3][r] = v.w;
        }
        // W tile: 32 k x 64 cols
#pragma unroll
        for (int i = 0; i < 4; i++) {
            int idx = tid + i * 128;
            int k   = idx >> 4;               // 0..31
            int og  = idx & 15;               // 0..15
            float4 v = *(const float4*)(W + (size_t)(k0 + k) * 64 + og * 4);
            *(float4*)&Ws[k][og * 4] = v;
        }
        __syncthreads();

#pragma unroll 8
        for (int kk = 0; kk < 32; kk++) {
            float av[4];
            av[0] = Xs[kk][ty4 + 0];
            av[1] = Xs[kk][ty4 + 1];
            av[2] = Xs[kk][ty4 + 2];
            av[3] = Xs[kk][ty4 + 3];
            float wv[8];
            *(float4*)&wv[0] = *(const float4*)&Ws[kk][tx8];
            *(float4*)&wv[4] = *(const float4*)&Ws[kk][tx8 + 4];
#pragma unroll
            for (int i = 0; i < 4; i++)
#pragma unroll
                for (int j = 0; j < 8; j++)
                    acc[i][j] = fmaf(av[i], wv[j], acc[i][j]);
        }
        __syncthreads();
    }

    float bv[8];
    if (bias != nullptr) {
#pragma unroll
        for (int j = 0; j < 8; j++) bv[j] = bias[tx8 + j];
    } else {
#pragma unroll
        for (int j = 0; j < 8; j++) bv[j] = 0.f;
    }

#pragma unroll
    for (int i = 0; i < 4; i++) {
        int r = row0 + ty4 + i;
        if (r < N_NODES) {
            float4 o0 = make_float4(acc[i][0] + bv[0], acc[i][1] + bv[1],
                                    acc[i][2] + bv[2], acc[i][3] + bv[3]);
            float4 o1 = make_float4(acc[i][4] + bv[4], acc[i][5] + bv[5],
                                    acc[i][6] + bv[6], acc[i][7] + bv[7]);
            *(float4*)(Out + (size_t)r * 64 + tx8)     = o0;
            *(float4*)(Out + (size_t)r * 64 + tx8 + 4) = o1;
        }
    }
}

// -------- SpMM: H[i] += (sum_{e in row i} A[col[e]]) * inv_deg[i] ----------
// one warp per destination node; each lane owns a float2 of the 64-dim row.
__global__ __launch_bounds__(256) void k_spmm(int asel, int hsel) {
    const float* __restrict__ A = getbuf(asel);
    float* __restrict__ H = getbuf(hsel);
    int gw   = (blockIdx.x * blockDim.x + threadIdx.x) >> 5;
    int lane = threadIdx.x & 31;
    if (gw >= N_NODES) return;
    int beg = g_rowptr[gw];
    int end = g_rowptr[gw + 1];
    float2 acc = make_float2(0.f, 0.f);
    for (int e = beg; e < end; e++) {
        int s = g_col[e];
        float2 v = *(const float2*)(A + (size_t)s * 64 + lane * 2);
        acc.x += v.x;
        acc.y += v.y;
    }
    float inv = g_inv[gw];
    float2* hp = (float2*)(H + (size_t)gw * 64 + lane * 2);
    float2 h = *hp;
    h.x = fmaf(acc.x, inv, h.x);
    h.y = fmaf(acc.y, inv, h.y);
    *hp = h;
}

// -------- BN statistics -----------------------------------------------------
__global__ __launch_bounds__(256) void k_stats(int hsel) {
    const float* __restrict__ H = getbuf(hsel);
    __shared__ float sh[256], sh2[256];
    int c  = threadIdx.x & 63;
    int rr = threadIdx.x >> 6;
    float s = 0.f, s2 = 0.f;
    for (int r = blockIdx.x * 4 + rr; r < N_NODES; r += gridDim.x * 4) {
        float v = H[(size_t)r * 64 + c];
        s  += v;
        s2 += v * v;
    }
    sh[threadIdx.x]  = s;
    sh2[threadIdx.x] = s2;
    __syncthreads();
    if (threadIdx.x < 64) {
        float a = sh[c] + sh[c + 64] + sh[c + 128] + sh[c + 192];
        float b = sh2[c] + sh2[c + 64] + sh2[c + 128] + sh2[c + 192];
        atomicAdd(&g_sum[c], a);
        atomicAdd(&g_sumsq[c], b);
    }
}

__global__ void k_finalize(const float* __restrict__ g, const float* __restrict__ be) {
    int c = threadIdx.x;
    if (c < 64) {
        float mu  = g_sum[c] / (float)N_NODES;
        float var = g_sumsq[c] / (float)N_NODES - mu * mu;
        float sc  = g[c] * rsqrtf(var + 1e-5f);
        g_scale[c] = sc;
        g_shift[c] = be[c] - mu * sc;
    }
}

__global__ void k_bnrelu(int hsel) {
    float* __restrict__ H = getbuf(hsel);
    int i = blockIdx.x * blockDim.x + threadIdx.x;   // float4 index
    if (i < N_NODES * 16) {
        float4 v = ((float4*)H)[i];
        int c = (i & 15) * 4;
        v.x = fmaxf(fmaf(v.x, g_scale[c + 0], g_shift[c + 0]), 0.f);
        v.y = fmaxf(fmaf(v.y, g_scale[c + 1], g_shift[c + 1]), 0.f);
        v.z = fmaxf(fmaf(v.z, g_scale[c + 2], g_shift[c + 2]), 0.f);
        v.w = fmaxf(fmaf(v.w, g_scale[c + 3], g_shift[c + 3]), 0.f);
        ((float4*)H)[i] = v;
    }
}

// -------- fusion MLP: relu([h, xgb] @ Wf1 + bf1) @ Wf2 + bf2 ---------------
__global__ __launch_bounds__(256) void k_fusion(int hsel,
                                                const float* __restrict__ xgb,
                                                const float* __restrict__ Wf1,
                                                const float* __restrict__ bf1,
                                                const float* __restrict__ Wf2,
                                                const float* __restrict__ bf2,
                                                float* __restrict__ out) {
    const float* __restrict__ H = getbuf(hsel);
    __shared__ float sW[65 * 64];
    __shared__ float sb1[64];
    __shared__ float sW2[64];
    __shared__ float sb2;
    for (int i = threadIdx.x; i < 65 * 64; i += 256) sW[i] = Wf1[i];
    if (threadIdx.x < 64) {
        sb1[threadIdx.x] = bf1[threadIdx.x];
        sW2[threadIdx.x] = Wf2[threadIdx.x];
    }
    if (threadIdx.x == 0) sb2 = bf2[0];
    __syncthreads();

    int node = blockIdx.x * 256 + threadIdx.x;
    if (node >= N_NODES) return;

    const float4* hp = (const float4*)(H + (size_t)node * 64);
    float4 acc[16];
#pragma unroll
    for (int jg = 0; jg < 16; jg++) acc[jg] = ((const float4*)sb1)[jg];

    for (int kc = 0; kc < 8; kc++) {
        float  hv[8];
        float4 h0 = hp[kc * 2];
        float4 h1 = hp[kc * 2 + 1];
        hv[0] = h0.x; hv[1] = h0.y; hv[2] = h0.z; hv[3] = h0.w;
        hv[4] = h1.x; hv[5] = h1.y; hv[6] = h1.z; hv[7] = h1.w;
#pragma unroll
        for (int kk = 0; kk < 8; kk++) {
            const float* wr = &sW[(kc * 8 + kk) * 64];
#pragma unroll
            for (int jg = 0; jg < 16; jg++) {
                float4 w = *(const float4*)&wr[jg * 4];
                acc[jg].x = fmaf(hv[kk], w.x, acc[jg].x);
                acc[jg].y = fmaf(hv[kk], w.y, acc[jg].y);
                acc[jg].z = fmaf(hv[kk], w.z, acc[jg].z);
                acc[jg].w = fmaf(hv[kk], w.w, acc[jg].w);
            }
        }
    }

    float xg    = xgb[node];
    float logit = sb2;
#pragma unroll
    for (int jg = 0; jg < 16; jg++) {
        float4 w = *(const float4*)&sW[64 * 64 + jg * 4];
        float4 a = acc[jg];
        a.x = fmaxf(fmaf(xg, w.x, a.x), 0.f);
        a.y = fmaxf(fmaf(xg, w.y, a.y), 0.f);
        a.z = fmaxf(fmaf(xg, w.z, a.z), 0.f);
        a.w = fmaxf(fmaf(xg, w.w, a.w), 0.f);
        float4 v2 = *(const float4*)&sW2[jg * 4];
        logit += a.x * v2.x + a.y * v2.y + a.z * v2.z + a.w * v2.w;
    }
    out[node] = logit;
}

// ---------------------------------------------------------------------------
extern "C" void kernel_launch(void* const* d_in, const int* in_sizes, int n_in,
                              void* d_out, int out_size) {
    const float* x    = (const float*)d_in[0];
    const int*   ei   = (const int*)d_in[1];      // int32 on the wire!
    const float* xgb  = (const float*)d_in[2];
    const float* W1l  = (const float*)d_in[3];
    const float* b1   = (const float*)d_in[4];
    const float* W1r  = (const float*)d_in[5];
    const float* g1   = (const float*)d_in[6];
    const float* be1  = (const float*)d_in[7];
    const float* W2l  = (const float*)d_in[8];
    const float* b2   = (const float*)d_in[9];
    const float* W2r  = (const float*)d_in[10];
    const float* g2   = (const float*)d_in[11];
    const float* be2  = (const float*)d_in[12];
    const float* W3l  = (const float*)d_in[13];
    const float* b3   = (const float*)d_in[14];
    const float* W3r  = (const float*)d_in[15];
    const float* g3   = (const float*)d_in[16];
    const float* be3  = (const float*)d_in[17];
    const float* Wf1  = (const float*)d_in[18];
    const float* bf1  = (const float*)d_in[19];
    const float* Wf2  = (const float*)d_in[20];
    const float* bf2  = (const float*)d_in[21];
    float*       out  = (float*)d_out;

    const int EB = (N_EDGES + 255) / 256;
    const int GB = (N_NODES + 63) / 64;          // gemm blocks
    const int SB = (N_NODES * 32 + 255) / 256;   // spmm blocks (warp/node)
    const int VB = (N_NODES * 16 + 255) / 256;   // bnrelu blocks (float4)
    const int FB = (N_NODES + 255) / 256;        // fusion blocks

    // CSR build
    k_zero_deg<<<(N_NODES + 255) / 256, 256>>>();
    k_hist<<<EB, 256>>>(ei);
    k_scan<<<1, 1024>>>();
    k_scatter<<<EB, 256>>>(ei);

    // ---- layer 1 (D=128): A=x@W1l -> bufA(0); H=x@W1r+b1 -> buf1(2) ----
    k_gemm<128><<<GB, 128>>>(x, -1, W1l, nullptr, 0);
    k_gemm<128><<<GB, 128>>>(x, -1, W1r, b1, 2);
    k_spmm<<<SB, 256>>>(0, 2);
    k_zero_stats<<<1, 64>>>();
    k_stats<<<512, 256>>>(2);
    k_finalize<<<1, 64>>>(g1, be1);
    k_bnrelu<<<VB, 256>>>(2);

    // ---- layer 2 (D=64): in buf1(2) -> out buf0(1) ----
    k_gemm<64><<<GB, 128>>>(nullptr, 2, W2l, nullptr, 0);
    k_gemm<64><<<GB, 128>>>(nullptr, 2, W2r, b2, 1);
    k_spmm<<<SB, 256>>>(0, 1);
    k_zero_stats<<<1, 64>>>();
    k_stats<<<512, 256>>>(1);
    k_finalize<<<1, 64>>>(g2, be2);
    k_bnrelu<<<VB, 256>>>(1);

    // ---- layer 3 (D=64): in buf0(1) -> out buf1(2) ----
    k_gemm<64><<<GB, 128>>>(nullptr, 1, W3l, nullptr, 0);
    k_gemm<64><<<GB, 128>>>(nullptr, 1, W3r, b3, 2);
    k_spmm<<<SB, 256>>>(0, 2);
    k_zero_stats<<<1, 64>>>();
    k_stats<<<512, 256>>>(2);
    k_finalize<<<1, 64>>>(g3, be3);
    k_bnrelu<<<VB, 256>>>(2);

    // ---- fusion MLP ----
    k_fusion<<<FB, 256>>>(2, xgb, Wf1, bf1, Wf2, bf2, out);
}

// round 4
// speedup vs baseline: 1.0311x; 1.0311x over previous
#include <cuda_runtime.h>

// ---------------------------------------------------------------------------
// HybridSAGEClassifier on GB300 — fused fp32 pipeline (R4).
//   CSR build once, then per layer ONE merged GEMM (A=X@Wl | H=X@Wr+b, with
//   BN+ReLU of the previous layer fused into the X loads), ONE SpMM kernel
//   that also accumulates BN statistics, and a tiny finalize. Fusion MLP
//   applies the last BN on the fly.
// edge_index is int32 on the wire (JAX x64 disabled).
// ---------------------------------------------------------------------------

static constexpr int N_NODES = 100000;
static constexpr int N_EDGES = 1200000;

// -------- device-global scratch --------------------------------------------
__device__ __align__(128) int   g_deg[N_NODES];
__device__ __align__(128) int   g_rowptr[N_NODES + 1];
__device__ __align__(128) int   g_cursor[N_NODES];
__device__ __align__(128) int   g_col[N_EDGES];
__device__ __align__(128) float g_inv[N_NODES];
__device__ __align__(128) float g_bufA[(size_t)N_NODES * 64];
__device__ __align__(128) float g_buf0[(size_t)N_NODES * 64];
__device__ __align__(128) float g_buf1[(size_t)N_NODES * 64];
__device__ __align__(128) float g_sum[64];
__device__ __align__(128) float g_sumsq[64];
__device__ __align__(128) float g_scale[64];
__device__ __align__(128) float g_shift[64];

__device__ __forceinline__ float* getbuf(int s) {
    return (s == 0) ? g_bufA : (s == 1) ? g_buf0 : g_buf1;
}
__device__ __forceinline__ int clampN(int v) {
    return (v < 0) ? 0 : (v >= N_NODES ? N_NODES - 1 : v);
}

// -------- CSR build --------------------------------------------------------
__global__ void k_zero_deg() {
    int i = blockIdx.x * blockDim.x + threadIdx.x;
    if (i < N_NODES) g_deg[i] = 0;
}
__global__ void k_zero_stats() {
    int i = threadIdx.x;
    if (i < 64) { g_sum[i] = 0.f; g_sumsq[i] = 0.f; }
}
__global__ void k_hist(const int* __restrict__ ei) {
    int e = blockIdx.x * blockDim.x + threadIdx.x;
    if (e < N_EDGES) atomicAdd(&g_deg[clampN(ei[N_EDGES + e])], 1);
}
__global__ void k_scan() {
    __shared__ int sh[1024];
    int tid = threadIdx.x;
    const int C = (N_NODES + 1023) / 1024;
    int beg = tid * C, end = beg + C;
    if (beg > N_NODES) beg = N_NODES;
    if (end > N_NODES) end = N_NODES;
    int s = 0;
    for (int i = beg; i < end; i++) s += g_deg[i];
    sh[tid] = s;
    __syncthreads();
    for (int off = 1; off < 1024; off <<= 1) {
        int add = (tid >= off) ? sh[tid - off] : 0;
        __syncthreads();
        sh[tid] += add;
        __syncthreads();
    }
    int base = (tid == 0) ? 0 : sh[tid - 1];
    for (int i = beg; i < end; i++) {
        g_rowptr[i] = base;
        g_cursor[i] = base;
        int d = g_deg[i];
        g_inv[i] = 1.0f / (float)(d > 0 ? d : 1);
        base += d;
    }
    if (tid == 0) g_rowptr[N_NODES] = N_EDGES;
}
__global__ void k_scatter(const int* __restrict__ ei) {
    int e = blockIdx.x * blockDim.x + threadIdx.x;
    if (e < N_EDGES) {
        int d = clampN(ei[N_EDGES + e]);
        int p = atomicAdd(&g_cursor[d], 1);
        g_col[p] = clampN(ei[e]);
    }
}

// -------- merged GEMM ------------------------------------------------------
// Computes simultaneously:
//   A[r, 0:64]  = BNx(X)[r,:] @ Wl          -> getbuf(oselA)
//   H[r, 0:64]  = BNx(X)[r,:] @ Wr + bias   -> getbuf(oselH)
// BNx = identity (BN=false) or relu(x*g_scale + g_shift) per channel.
// Block tile 128 rows x 128 cols, 256 threads, 8x8 microtile, reg-double-buffered.
template <int D, bool BN>
__global__ __launch_bounds__(256) void k_gemm2(const float* __restrict__ Xext,
                                               int xsel,
                                               const float* __restrict__ Wl,
                                               const float* __restrict__ Wr,
                                               const float* __restrict__ bias,
                                               int oselA, int oselH) {
    const float* __restrict__ X = (xsel < 0) ? Xext : getbuf(xsel);
    float* __restrict__ OA = getbuf(oselA);
    float* __restrict__ OH = getbuf(oselH);

    __shared__ float Xs[16][132];    // [k][row], stride 132 keeps LDS.128 align
    __shared__ float Ws[16][128];    // [k][col]  (cols 0..63 = Wl, 64..127 = Wr)
    __shared__ float ssc[64], ssh[64];

    const int tid  = threadIdx.x;
    const int row0 = blockIdx.x * 128;
    const int ty   = tid >> 4;        // 0..15  -> rows ty*8..ty*8+7
    const int tx   = tid & 15;        // 0..15  -> cols tx*8..tx*8+7
    const int ty8  = ty * 8;
    const int tx8  = tx * 8;

    if (BN) {
        if (tid < 64) { ssc[tid] = g_scale[tid]; ssh[tid] = g_shift[tid]; }
        __syncthreads();
    }

    // per-thread load coords (X): idx over 512 float4s
    const int xr_r0 = (tid * 2) >> 2;           // row within tile for i=0
    const int xr_j0 = (tid * 2) & 3;            // f4 col for i=0
    const int xr_r1 = (tid * 2 + 1) >> 2;
    const int xr_j1 = (tid * 2 + 1) & 3;
    // W coords: idx over 512 float4s, 32 f4 per k-row
    const int wk0 = (tid * 2) >> 5, wc0 = (tid * 2) & 31;
    const int wk1 = (tid * 2 + 1) >> 5, wc1 = (tid * 2 + 1) & 31;

    float acc[8][8];
#pragma unroll
    for (int i = 0; i < 8; i++)
#pragma unroll
        for (int j = 0; j < 8; j++) acc[i][j] = 0.f;

    const int T = D / 16;
    float4 xr[2], wr[2];

    auto loadX = [&](int k0, float4* r) {
        int rr0 = row0 + xr_r0; if (rr0 >= N_NODES) rr0 = N_NODES - 1;
        int rr1 = row0 + xr_r1; if (rr1 >= N_NODES) rr1 = N_NODES - 1;
        r[0] = *(const float4*)(X + (size_t)rr0 * D + k0 + xr_j0 * 4);
        r[1] = *(const float4*)(X + (size_t)rr1 * D + k0 + xr_j1 * 4);
    };
    auto loadW = [&](int k0, float4* r) {
        r[0] = (wc0 < 16) ? *(const float4*)(Wl + (size_t)(k0 + wk0) * 64 + wc0 * 4)
                          : *(const float4*)(Wr + (size_t)(k0 + wk0) * 64 + (wc0 - 16) * 4);
        r[1] = (wc1 < 16) ? *(const float4*)(Wl + (size_t)(k0 + wk1) * 64 + wc1 * 4)
                          : *(const float4*)(Wr + (size_t)(k0 + wk1) * 64 + (wc1 - 16) * 4);
    };
    auto bnv = [&](float v, int ch) -> float {
        if (BN) return fmaxf(fmaf(v, ssc[ch], ssh[ch]), 0.f);
        return v;
    };
    auto storeX = [&](int k0, const float4* r) {
        int c0 = k0 + xr_j0 * 4;
        Xs[xr_j0 * 4 + 0][xr_r0] = bnv(r[0].x, (c0 + 0) & 63);
        Xs[xr_j0 * 4 + 1][xr_r0] = bnv(r[0].y, (c0 + 1) & 63);
        Xs[xr_j0 * 4 + 2][xr_r0] = bnv(r[0].z, (c0 + 2) & 63);
        Xs[xr_j0 * 4 + 3][xr_r0] = bnv(r[0].w, (c0 + 3) & 63);
        int c1 = k0 + xr_j1 * 4;
        Xs[xr_j1 * 4 + 0][xr_r1] = bnv(r[1].x, (c1 + 0) & 63);
        Xs[xr_j1 * 4 + 1][xr_r1] = bnv(r[1].y, (c1 + 1) & 63);
        Xs[xr_j1 * 4 + 2][xr_r1] = bnv(r[1].z, (c1 + 2) & 63);
        Xs[xr_j1 * 4 + 3][xr_r1] = bnv(r[1].w, (c1 + 3) & 63);
    };
    auto storeW = [&](const float4* r) {
        int c0 = (wc0 < 16) ? wc0 * 4 : 64 + (wc0 - 16) * 4;
        int c1 = (wc1 < 16) ? wc1 * 4 : 64 + (wc1 - 16) * 4;
        *(float4*)&Ws[wk0][c0] = r[0];
        *(float4*)&Ws[wk1][c1] = r[1];
    };

    loadX(0, xr);
    loadW(0, wr);
    int k0 = 0;
    for (int t = 0; t < T; t++) {
        storeX(k0, xr);
        storeW(wr);
        __syncthreads();
        if (t + 1 < T) { loadX(k0 + 16, xr); loadW(k0 + 16, wr); }

#pragma unroll
        for (int kk = 0; kk < 16; kk++) {
            float av[8], wv[8];
            *(float4*)&av[0] = *(const float4*)&Xs[kk][ty8];
            *(float4*)&av[4] = *(const float4*)&Xs[kk][ty8 + 4];
            *(float4*)&wv[0] = *(const float4*)&Ws[kk][tx8];
            *(float4*)&wv[4] = *(const float4*)&Ws[kk][tx8 + 4];
#pragma unroll
            for (int i = 0; i < 8; i++)
#pragma unroll
                for (int j = 0; j < 8; j++)
                    acc[i][j] = fmaf(av[i], wv[j], acc[i][j]);
        }
        __syncthreads();
        k0 += 16;
    }

    // epilogue: cols tx8<64 -> A (no bias), else H (+bias)
    const bool isH = (tx8 >= 64);
    float* __restrict__ O = isH ? OH : OA;
    const int oc = isH ? (tx8 - 64) : tx8;
    float bv[8];
#pragma unroll
    for (int j = 0; j < 8; j++) bv[j] = isH ? bias[oc + j] : 0.f;

#pragma unroll
    for (int i = 0; i < 8; i++) {
        int r = row0 + ty8 + i;
        if (r < N_NODES) {
            float4 o0 = make_float4(acc[i][0] + bv[0], acc[i][1] + bv[1],
                                    acc[i][2] + bv[2], acc[i][3] + bv[3]);
            float4 o1 = make_float4(acc[i][4] + bv[4], acc[i][5] + bv[5],
                                    acc[i][6] + bv[6], acc[i][7] + bv[7]);
            *(float4*)(O + (size_t)r * 64 + oc)     = o0;
            *(float4*)(O + (size_t)r * 64 + oc + 4) = o1;
        }
    }
}

// -------- SpMM + BN statistics ---------------------------------------------
// H[i] += (sum_{e in row i} A[col[e]]) * inv_deg[i];  also accumulate
// per-channel sum / sumsq of the final H into g_sum / g_sumsq.
__global__ __launch_bounds__(256) void k_spmm_stats(int asel, int hsel) {
    const float* __restrict__ A = getbuf(asel);
    float* __restrict__ H = getbuf(hsel);
    __shared__ float ssum[64], ssq[64];
    if (threadIdx.x < 64) { ssum[threadIdx.x] = 0.f; ssq[threadIdx.x] = 0.f; }
    __syncthreads();

    int gw   = (blockIdx.x * blockDim.x + threadIdx.x) >> 5;
    int lane = threadIdx.x & 31;
    if (gw < N_NODES) {
        int beg = g_rowptr[gw];
        int end = g_rowptr[gw + 1];
        float2 acc = make_float2(0.f, 0.f);
        for (int e = beg; e < end; e++) {
            int s = g_col[e];
            float2 v = *(const float2*)(A + (size_t)s * 64 + lane * 2);
            acc.x += v.x;
            acc.y += v.y;
        }
        float inv = g_inv[gw];
        float2* hp = (float2*)(H + (size_t)gw * 64 + lane * 2);
        float2 h = *hp;
        h.x = fmaf(acc.x, inv, h.x);
        h.y = fmaf(acc.y, inv, h.y);
        *hp = h;
        atomicAdd(&ssum[lane * 2],     h.x);
        atomicAdd(&ssum[lane * 2 + 1], h.y);
        atomicAdd(&ssq[lane * 2],      h.x * h.x);
        atomicAdd(&ssq[lane * 2 + 1],  h.y * h.y);
    }
    __syncthreads();
    if (threadIdx.x < 64) {
        atomicAdd(&g_sum[threadIdx.x],   ssum[threadIdx.x]);
        atomicAdd(&g_sumsq[threadIdx.x], ssq[threadIdx.x]);
    }
}

// -------- BN finalize (also re-zeroes accumulators for next layer) ----------
__global__ void k_finalize(const float* __restrict__ g, const float* __restrict__ be) {
    int c = threadIdx.x;
    if (c < 64) {
        float mu  = g_sum[c] / (float)N_NODES;
        float var = g_sumsq[c] / (float)N_NODES - mu * mu;
        float sc  = g[c] * rsqrtf(var + 1e-5f);
        g_scale[c] = sc;
        g_shift[c] = be[c] - mu * sc;
        g_sum[c]   = 0.f;
        g_sumsq[c] = 0.f;
    }
}

// -------- fusion MLP (applies layer-3 BN+ReLU on the fly) -------------------
__global__ __launch_bounds__(256) void k_fusion(int hsel,
                                                const float* __restrict__ xgb,
                                                const float* __restrict__ Wf1,
                                                const float* __restrict__ bf1,
                                                const float* __restrict__ Wf2,
                                                const float* __restrict__ bf2,
                                                float* __restrict__ out) {
    const float* __restrict__ H = getbuf(hsel);
    __shared__ float sW[65 * 64];
    __shared__ float sb1[64], sW2[64], ssc[64], ssh[64];
    __shared__ float sb2;
    for (int i = threadIdx.x; i < 65 * 64; i += 256) sW[i] = Wf1[i];
    if (threadIdx.x < 64) {
        sb1[threadIdx.x] = bf1[threadIdx.x];
        sW2[threadIdx.x] = Wf2[threadIdx.x];
        ssc[threadIdx.x] = g_scale[threadIdx.x];
        ssh[threadIdx.x] = g_shift[threadIdx.x];
    }
    if (threadIdx.x == 0) sb2 = bf2[0];
    __syncthreads();

    int node = blockIdx.x * 256 + threadIdx.x;
    if (node >= N_NODES) return;

    const float4* hp = (const float4*)(H + (size_t)node * 64);
    float4 acc[16];
#pragma unroll
    for (int jg = 0; jg < 16; jg++) acc[jg] = ((const float4*)sb1)[jg];

    for (int kc = 0; kc < 8; kc++) {
        float  hv[8];
        float4 h0 = hp[kc * 2];
        float4 h1 = hp[kc * 2 + 1];
        hv[0] = h0.x; hv[1] = h0.y; hv[2] = h0.z; hv[3] = h0.w;
        hv[4] = h1.x; hv[5] = h1.y; hv[6] = h1.z; hv[7] = h1.w;
#pragma unroll
        for (int kk = 0; kk < 8; kk++) {
            int ch = kc * 8 + kk;
            float x = fmaxf(fmaf(hv[kk], ssc[ch], ssh[ch]), 0.f);
            const float* wr = &sW[ch * 64];
#pragma unroll
            for (int jg = 0; jg < 16; jg++) {
                float4 w = *(const float4*)&wr[jg * 4];
                acc[jg].x = fmaf(x, w.x, acc[jg].x);
                acc[jg].y = fmaf(x, w.y, acc[jg].y);
                acc[jg].z = fmaf(x, w.z, acc[jg].z);
                acc[jg].w = fmaf(x, w.w, acc[jg].w);
            }
        }
    }

    float xg    = xgb[node];
    float logit = sb2;
#pragma unroll
    for (int jg = 0; jg < 16; jg++) {
        float4 w = *(const float4*)&sW[64 * 64 + jg * 4];
        float4 a = acc[jg];
        a.x = fmaxf(fmaf(xg, w.x, a.x), 0.f);
        a.y = fmaxf(fmaf(xg, w.y, a.y), 0.f);
        a.z = fmaxf(fmaf(xg, w.z, a.z), 0.f);
        a.w = fmaxf(fmaf(xg, w.w, a.w), 0.f);
        float4 v2 = *(const float4*)&sW2[jg * 4];
        logit += a.x * v2.x + a.y * v2.y + a.z * v2.z + a.w * v2.w;
    }
    out[node] = logit;
}

// ---------------------------------------------------------------------------
extern "C" void kernel_launch(void* const* d_in, const int* in_sizes, int n_in,
                              void* d_out, int out_size) {
    const float* x    = (const float*)d_in[0];
    const int*   ei   = (const int*)d_in[1];      // int32 on the wire
    const float* xgb  = (const float*)d_in[2];
    const float* W1l  = (const float*)d_in[3];
    const float* b1   = (const float*)d_in[4];
    const float* W1r  = (const float*)d_in[5];
    const float* g1   = (const float*)d_in[6];
    const float* be1  = (const float*)d_in[7];
    const float* W2l  = (const float*)d_in[8];
    const float* b2   = (const float*)d_in[9];
    const float* W2r  = (const float*)d_in[10];
    const float* g2   = (const float*)d_in[11];
    const float* be2  = (const float*)d_in[12];
    const float* W3l  = (const float*)d_in[13];
    const float* b3   = (const float*)d_in[14];
    const float* W3r  = (const float*)d_in[15];
    const float* g3   = (const float*)d_in[16];
    const float* be3  = (const float*)d_in[17];
    const float* Wf1  = (const float*)d_in[18];
    const float* bf1  = (const float*)d_in[19];
    const float* Wf2  = (const float*)d_in[20];
    const float* bf2  = (const float*)d_in[21];
    float*       out  = (float*)d_out;

    const int EB = (N_EDGES + 255) / 256;
    const int GB = (N_NODES + 127) / 128;        // merged-gemm blocks
    const int SB = (N_NODES * 32 + 255) / 256;   // spmm blocks (warp/node)
    const int FB = (N_NODES + 255) / 256;        // fusion blocks

    // CSR build + stat init
    k_zero_deg<<<(N_NODES + 255) / 256, 256>>>();
    k_hist<<<EB, 256>>>(ei);
    k_scan<<<1, 1024>>>();
    k_scatter<<<EB, 256>>>(ei);
    k_zero_stats<<<1, 64>>>();

    // layer 1: x (D=128, no BN) -> A in bufA(0), H in buf1(2)
    k_gemm2<128, false><<<GB, 256>>>(x, -1, W1l, W1r, b1, 0, 2);
    k_spmm_stats<<<SB, 256>>>(0, 2);
    k_finalize<<<1, 64>>>(g1, be1);

    // layer 2: BN1(buf1) (D=64) -> A in bufA(0), H in buf0(1)
    k_gemm2<64, true><<<GB, 256>>>(nullptr, 2, W2l, W2r, b2, 0, 1);
    k_spmm_stats<<<SB, 256>>>(0, 1);
    k_finalize<<<1, 64>>>(g2, be2);

    // layer 3: BN2(buf0) (D=64) -> A in bufA(0), H in buf1(2)
    k_gemm2<64, true><<<GB, 256>>>(nullptr, 1, W3l, W3r, b3, 0, 2);
    k_spmm_stats<<<SB, 256>>>(0, 2);
    k_finalize<<<1, 64>>>(g3, be3);

    // fusion (applies BN3 on the fly)
    k_fusion<<<FB, 256>>>(2, xgb, Wf1, bf1, Wf2, bf2, out);
}

// round 5
// speedup vs baseline: 1.4475x; 1.4038x over previous
#include <cuda_runtime.h>

// ---------------------------------------------------------------------------
// HybridSAGEClassifier on GB300 — R5.
//   vs R4: (1) SpMM uses shfl-broadcast batched gathers (kills the serial
//   col->gather dependency, MLP ~1 -> ~8), (2) CSR prefix scan parallelized
//   into 3 small kernels, (3) launches reordered so the big layer-1 GEMM
//   lands in the ncu-profiled slot (4th kernel launch).
// edge_index is int32 on the wire.
// ---------------------------------------------------------------------------

static constexpr int N_NODES = 100000;
static constexpr int N_EDGES = 1200000;
static constexpr int SCHUNK  = 1024;
static constexpr int SNB     = (N_NODES + SCHUNK - 1) / SCHUNK;   // 98

// -------- device-global scratch --------------------------------------------
__device__ __align__(128) int   g_deg[N_NODES];
__device__ __align__(128) int   g_rowptr[N_NODES + 1];
__device__ __align__(128) int   g_cursor[N_NODES];
__device__ __align__(128) int   g_col[N_EDGES];
__device__ __align__(128) float g_inv[N_NODES];
__device__ __align__(128) int   g_bsum[SNB];
__device__ __align__(128) int   g_boff[SNB];
__device__ __align__(128) float g_bufA[(size_t)N_NODES * 64];
__device__ __align__(128) float g_buf0[(size_t)N_NODES * 64];
__device__ __align__(128) float g_buf1[(size_t)N_NODES * 64];
__device__ __align__(128) float g_sum[64];
__device__ __align__(128) float g_sumsq[64];
__device__ __align__(128) float g_scale[64];
__device__ __align__(128) float g_shift[64];

__device__ __forceinline__ float* getbuf(int s) {
    return (s == 0) ? g_bufA : (s == 1) ? g_buf0 : g_buf1;
}
__device__ __forceinline__ int clampN(int v) {
    return (v < 0) ? 0 : (v >= N_NODES ? N_NODES - 1 : v);
}

// -------- CSR build --------------------------------------------------------
__global__ void k_zero_deg() {
    int i = blockIdx.x * blockDim.x + threadIdx.x;
    if (i < N_NODES) g_deg[i] = 0;
}
__global__ void k_zero_stats() {
    int i = threadIdx.x;
    if (i < 64) { g_sum[i] = 0.f; g_sumsq[i] = 0.f; }
}
__global__ void k_hist(const int* __restrict__ ei) {
    int e = blockIdx.x * blockDim.x + threadIdx.x;
    if (e < N_EDGES) atomicAdd(&g_deg[clampN(ei[N_EDGES + e])], 1);
}

// 3-phase exclusive prefix scan of g_deg -> g_rowptr/g_cursor/g_inv
__global__ __launch_bounds__(256) void k_scan1() {
    __shared__ int sh[256];
    int b = blockIdx.x, t = threadIdx.x;
    int base = b * SCHUNK + t * 4;
    int s = 0;
#pragma unroll
    for (int i = 0; i < 4; i++) {
        int idx = base + i;
        if (idx < N_NODES) s += g_deg[idx];
    }
    sh[t] = s;
    __syncthreads();
    for (int off = 128; off > 0; off >>= 1) {
        if (t < off) sh[t] += sh[t + off];
        __syncthreads();
    }
    if (t == 0) g_bsum[b] = sh[0];
}
__global__ __launch_bounds__(128) void k_scan2() {
    __shared__ int sh[128];
    int t = threadIdx.x;
    int v = (t < SNB) ? g_bsum[t] : 0;
    sh[t] = v;
    __syncthreads();
    for (int off = 1; off < 128; off <<= 1) {
        int a = (t >= off) ? sh[t - off] : 0;
        __syncthreads();
        sh[t] += a;
        __syncthreads();
    }
    if (t < SNB) g_boff[t] = sh[t] - v;   // exclusive
}
__global__ __launch_bounds__(256) void k_scan3() {
    __shared__ int sh[256];
    int b = blockIdx.x, t = threadIdx.x;
    int base = b * SCHUNK + t * 4;
    int local[4];
    int s = 0;
#pragma unroll
    for (int i = 0; i < 4; i++) {
        int idx = base + i;
        local[i] = (idx < N_NODES) ? g_deg[idx] : 0;
        s += local[i];
    }
    sh[t] = s;
    __syncthreads();
    for (int off = 1; off < 256; off <<= 1) {
        int a = (t >= off) ? sh[t - off] : 0;
        __syncthreads();
        sh[t] += a;
        __syncthreads();
    }
    int run = g_boff[b] + sh[t] - s;      // exclusive offset for this thread
#pragma unroll
    for (int i = 0; i < 4; i++) {
        int idx = base + i;
        if (idx < N_NODES) {
            g_rowptr[idx] = run;
            g_cursor[idx] = run;
            int d = local[i];
            g_inv[idx] = 1.0f / (float)(d > 0 ? d : 1);
            run += d;
        }
    }
    if (b == 0 && t == 0) g_rowptr[N_NODES] = N_EDGES;
}
__global__ void k_scatter(const int* __restrict__ ei) {
    int e = blockIdx.x * blockDim.x + threadIdx.x;
    if (e < N_EDGES) {
        int d = clampN(ei[N_EDGES + e]);
        int p = atomicAdd(&g_cursor[d], 1);
        g_col[p] = clampN(ei[e]);
    }
}

// -------- merged GEMM ------------------------------------------------------
//   A[r, 0:64]  = BNx(X)[r,:] @ Wl          -> getbuf(oselA)
//   H[r, 0:64]  = BNx(X)[r,:] @ Wr + bias   -> getbuf(oselH)
// BNx = identity (BN=false) or relu(x*g_scale + g_shift) per channel.
// Block tile 128 rows x 128 cols, 256 threads, 8x8 microtile, reg-double-buffered.
template <int D, bool BN>
__global__ __launch_bounds__(256) void k_gemm2(const float* __restrict__ Xext,
                                               int xsel,
                                               const float* __restrict__ Wl,
                                               const float* __restrict__ Wr,
                                               const float* __restrict__ bias,
                                               int oselA, int oselH) {
    const float* __restrict__ X = (xsel < 0) ? Xext : getbuf(xsel);
    float* __restrict__ OA = getbuf(oselA);
    float* __restrict__ OH = getbuf(oselH);

    __shared__ float Xs[16][132];
    __shared__ float Ws[16][128];
    __shared__ float ssc[64], ssh[64];

    const int tid  = threadIdx.x;
    const int row0 = blockIdx.x * 128;
    const int ty8  = (tid >> 4) * 8;
    const int tx8  = (tid & 15) * 8;

    if (BN) {
        if (tid < 64) { ssc[tid] = g_scale[tid]; ssh[tid] = g_shift[tid]; }
        __syncthreads();
    }

    const int xr_r0 = (tid * 2) >> 2;
    const int xr_j0 = (tid * 2) & 3;
    const int xr_r1 = (tid * 2 + 1) >> 2;
    const int xr_j1 = (tid * 2 + 1) & 3;
    const int wk0 = (tid * 2) >> 5, wc0 = (tid * 2) & 31;
    const int wk1 = (tid * 2 + 1) >> 5, wc1 = (tid * 2 + 1) & 31;

    float acc[8][8];
#pragma unroll
    for (int i = 0; i < 8; i++)
#pragma unroll
        for (int j = 0; j < 8; j++) acc[i][j] = 0.f;

    const int T = D / 16;
    float4 xr[2], wr[2];

    auto loadX = [&](int k0, float4* r) {
        int rr0 = row0 + xr_r0; if (rr0 >= N_NODES) rr0 = N_NODES - 1;
        int rr1 = row0 + xr_r1; if (rr1 >= N_NODES) rr1 = N_NODES - 1;
        r[0] = *(const float4*)(X + (size_t)rr0 * D + k0 + xr_j0 * 4);
        r[1] = *(const float4*)(X + (size_t)rr1 * D + k0 + xr_j1 * 4);
    };
    auto loadW = [&](int k0, float4* r) {
        r[0] = (wc0 < 16) ? *(const float4*)(Wl + (size_t)(k0 + wk0) * 64 + wc0 * 4)
                          : *(const float4*)(Wr + (size_t)(k0 + wk0) * 64 + (wc0 - 16) * 4);
        r[1] = (wc1 < 16) ? *(const float4*)(Wl + (size_t)(k0 + wk1) * 64 + wc1 * 4)
                          : *(const float4*)(Wr + (size_t)(k0 + wk1) * 64 + (wc1 - 16) * 4);
    };
    auto bnv = [&](float v, int ch) -> float {
        if (BN) return fmaxf(fmaf(v, ssc[ch], ssh[ch]), 0.f);
        return v;
    };
    auto storeX = [&](int k0, const float4* r) {
        int c0 = k0 + xr_j0 * 4;
        Xs[xr_j0 * 4 + 0][xr_r0] = bnv(r[0].x, (c0 + 0) & 63);
        Xs[xr_j0 * 4 + 1][xr_r0] = bnv(r[0].y, (c0 + 1) & 63);
        Xs[xr_j0 * 4 + 2][xr_r0] = bnv(r[0].z, (c0 + 2) & 63);
        Xs[xr_j0 * 4 + 3][xr_r0] = bnv(r[0].w, (c0 + 3) & 63);
        int c1 = k0 + xr_j1 * 4;
        Xs[xr_j1 * 4 + 0][xr_r1] = bnv(r[1].x, (c1 + 0) & 63);
        Xs[xr_j1 * 4 + 1][xr_r1] = bnv(r[1].y, (c1 + 1) & 63);
        Xs[xr_j1 * 4 + 2][xr_r1] = bnv(r[1].z, (c1 + 2) & 63);
        Xs[xr_j1 * 4 + 3][xr_r1] = bnv(r[1].w, (c1 + 3) & 63);
    };
    auto storeW = [&](const float4* r) {
        int c0 = (wc0 < 16) ? wc0 * 4 : 64 + (wc0 - 16) * 4;
        int c1 = (wc1 < 16) ? wc1 * 4 : 64 + (wc1 - 16) * 4;
        *(float4*)&Ws[wk0][c0] = r[0];
        *(float4*)&Ws[wk1][c1] = r[1];
    };

    loadX(0, xr);
    loadW(0, wr);
    int k0 = 0;
    for (int t = 0; t < T; t++) {
        storeX(k0, xr);
        storeW(wr);
        __syncthreads();
        if (t + 1 < T) { loadX(k0 + 16, xr); loadW(k0 + 16, wr); }

#pragma unroll
        for (int kk = 0; kk < 16; kk++) {
            float av[8], wv[8];
            *(float4*)&av[0] = *(const float4*)&Xs[kk][ty8];
            *(float4*)&av[4] = *(const float4*)&Xs[kk][ty8 + 4];
            *(float4*)&wv[0] = *(const float4*)&Ws[kk][tx8];
            *(float4*)&wv[4] = *(const float4*)&Ws[kk][tx8 + 4];
#pragma unroll
            for (int i = 0; i < 8; i++)
#pragma unroll
                for (int j = 0; j < 8; j++)
                    acc[i][j] = fmaf(av[i], wv[j], acc[i][j]);
        }
        __syncthreads();
        k0 += 16;
    }

    const bool isH = (tx8 >= 64);
    float* __restrict__ O = isH ? OH : OA;
    const int oc = isH ? (tx8 - 64) : tx8;
    float bv[8];
#pragma unroll
    for (int j = 0; j < 8; j++) bv[j] = isH ? bias[oc + j] : 0.f;

#pragma unroll
    for (int i = 0; i < 8; i++) {
        int r = row0 + ty8 + i;
        if (r < N_NODES) {
            float4 o0 = make_float4(acc[i][0] + bv[0], acc[i][1] + bv[1],
                                    acc[i][2] + bv[2], acc[i][3] + bv[3]);
            float4 o1 = make_float4(acc[i][4] + bv[4], acc[i][5] + bv[5],
                                    acc[i][6] + bv[6], acc[i][7] + bv[7]);
            *(float4*)(O + (size_t)r * 64 + oc)     = o0;
            *(float4*)(O + (size_t)r * 64 + oc + 4) = o1;
        }
    }
}

// -------- SpMM + BN statistics ---------------------------------------------
// One warp per dst node. Lanes cooperatively load 32 col indices (coalesced),
// broadcast each via shfl, then issue independent row gathers -> high MLP.
__global__ __launch_bounds__(256) void k_spmm_stats(int asel, int hsel) {
    const float* __restrict__ A = getbuf(asel);
    float* __restrict__ H = getbuf(hsel);
    __shared__ float ssum[64], ssq[64];
    if (threadIdx.x < 64) { ssum[threadIdx.x] = 0.f; ssq[threadIdx.x] = 0.f; }
    __syncthreads();

    int gw   = (blockIdx.x * blockDim.x + threadIdx.x) >> 5;
    int lane = threadIdx.x & 31;
    if (gw < N_NODES) {
        int beg = g_rowptr[gw];
        int end = g_rowptr[gw + 1];
        float2 acc = make_float2(0.f, 0.f);
        for (int e0 = beg; e0 < end; e0 += 32) {
            int c = (e0 + lane < end) ? g_col[e0 + lane] : 0;
            int n = end - e0;
            if (n > 32) n = 32;
#pragma unroll 4
            for (int i = 0; i < n; i++) {
                int s = __shfl_sync(0xffffffffu, c, i);
                float2 v = *(const float2*)(A + (size_t)s * 64 + lane * 2);
                acc.x += v.x;
                acc.y += v.y;
            }
        }
        float inv = g_inv[gw];
        float2* hp = (float2*)(H + (size_t)gw * 64 + lane * 2);
        float2 h = *hp;
        h.x = fmaf(acc.x, inv, h.x);
        h.y = fmaf(acc.y, inv, h.y);
        *hp = h;
        atomicAdd(&ssum[lane * 2],     h.x);
        atomicAdd(&ssum[lane * 2 + 1], h.y);
        atomicAdd(&ssq[lane * 2],      h.x * h.x);
        atomicAdd(&ssq[lane * 2 + 1],  h.y * h.y);
    }
    __syncthreads();
    if (threadIdx.x < 64) {
        atomicAdd(&g_sum[threadIdx.x],   ssum[threadIdx.x]);
        atomicAdd(&g_sumsq[threadIdx.x], ssq[threadIdx.x]);
    }
}

// -------- BN finalize (re-zeroes accumulators for next layer) ---------------
__global__ void k_finalize(const float* __restrict__ g, const float* __restrict__ be) {
    int c = threadIdx.x;
    if (c < 64) {
        float mu  = g_sum[c] / (float)N_NODES;
        float var = g_sumsq[c] / (float)N_NODES - mu * mu;
        float sc  = g[c] * rsqrtf(var + 1e-5f);
        g_scale[c] = sc;
        g_shift[c] = be[c] - mu * sc;
        g_sum[c]   = 0.f;
        g_sumsq[c] = 0.f;
    }
}

// -------- fusion MLP (applies layer-3 BN+ReLU on the fly) -------------------
__global__ __launch_bounds__(256) void k_fusion(int hsel,
                                                const float* __restrict__ xgb,
                                                const float* __restrict__ Wf1,
                                                const float* __restrict__ bf1,
                                                const float* __restrict__ Wf2,
                                                const float* __restrict__ bf2,
                                                float* __restrict__ out) {
    const float* __restrict__ H = getbuf(hsel);
    __shared__ float sW[65 * 64];
    __shared__ float sb1[64], sW2[64], ssc[64], ssh[64];
    __shared__ float sb2;
    for (int i = threadIdx.x; i < 65 * 64; i += 256) sW[i] = Wf1[i];
    if (threadIdx.x < 64) {
        sb1[threadIdx.x] = bf1[threadIdx.x];
        sW2[threadIdx.x] = Wf2[threadIdx.x];
        ssc[threadIdx.x] = g_scale[threadIdx.x];
        ssh[threadIdx.x] = g_shift[threadIdx.x];
    }
    if (threadIdx.x == 0) sb2 = bf2[0];
    __syncthreads();

    int node = blockIdx.x * 256 + threadIdx.x;
    if (node >= N_NODES) return;

    const float4* hp = (const float4*)(H + (size_t)node * 64);
    float4 acc[16];
#pragma unroll
    for (int jg = 0; jg < 16; jg++) acc[jg] = ((const float4*)sb1)[jg];

    for (int kc = 0; kc < 8; kc++) {
        float  hv[8];
        float4 h0 = hp[kc * 2];
        float4 h1 = hp[kc * 2 + 1];
        hv[0] = h0.x; hv[1] = h0.y; hv[2] = h0.z; hv[3] = h0.w;
        hv[4] = h1.x; hv[5] = h1.y; hv[6] = h1.z; hv[7] = h1.w;
#pragma unroll
        for (int kk = 0; kk < 8; kk++) {
            int ch = kc * 8 + kk;
            float x = fmaxf(fmaf(hv[kk], ssc[ch], ssh[ch]), 0.f);
            const float* wr = &sW[ch * 64];
#pragma unroll
            for (int jg = 0; jg < 16; jg++) {
                float4 w = *(const float4*)&wr[jg * 4];
                acc[jg].x = fmaf(x, w.x, acc[jg].x);
                acc[jg].y = fmaf(x, w.y, acc[jg].y);
                acc[jg].z = fmaf(x, w.z, acc[jg].z);
                acc[jg].w = fmaf(x, w.w, acc[jg].w);
            }
        }
    }

    float xg    = xgb[node];
    float logit = sb2;
#pragma unroll
    for (int jg = 0; jg < 16; jg++) {
        float4 w = *(const float4*)&sW[64 * 64 + jg * 4];
        float4 a = acc[jg];
        a.x = fmaxf(fmaf(xg, w.x, a.x), 0.f);
        a.y = fmaxf(fmaf(xg, w.y, a.y), 0.f);
        a.z = fmaxf(fmaf(xg, w.z, a.z), 0.f);
        a.w = fmaxf(fmaf(xg, w.w, a.w), 0.f);
        float4 v2 = *(const float4*)&sW2[jg * 4];
        logit += a.x * v2.x + a.y * v2.y + a.z * v2.z + a.w * v2.w;
    }
    out[node] = logit;
}

// ---------------------------------------------------------------------------
extern "C" void kernel_launch(void* const* d_in, const int* in_sizes, int n_in,
                              void* d_out, int out_size) {
    const float* x    = (const float*)d_in[0];
    const int*   ei   = (const int*)d_in[1];
    const float* xgb  = (const float*)d_in[2];
    const float* W1l  = (const float*)d_in[3];
    const float* b1   = (const float*)d_in[4];
    const float* W1r  = (const float*)d_in[5];
    const float* g1   = (const float*)d_in[6];
    const float* be1  = (const float*)d_in[7];
    const float* W2l  = (const float*)d_in[8];
    const float* b2   = (const float*)d_in[9];
    const float* W2r  = (const float*)d_in[10];
    const float* g2   = (const float*)d_in[11];
    const float* be2  = (const float*)d_in[12];
    const float* W3l  = (const float*)d_in[13];
    const float* b3   = (const float*)d_in[14];
    const float* W3r  = (const float*)d_in[15];
    const float* g3   = (const float*)d_in[16];
    const float* be3  = (const float*)d_in[17];
    const float* Wf1  = (const float*)d_in[18];
    const float* bf1  = (const float*)d_in[19];
    const float* Wf2  = (const float*)d_in[20];
    const float* bf2  = (const float*)d_in[21];
    float*       out  = (float*)d_out;

    const int EB = (N_EDGES + 255) / 256;
    const int GB = (N_NODES + 127) / 128;
    const int SB = (N_NODES * 32 + 255) / 256;
    const int FB = (N_NODES + 255) / 256;

    // 1-3: CSR hist + stat init
    k_zero_deg<<<(N_NODES + 255) / 256, 256>>>();
    k_hist<<<EB, 256>>>(ei);
    k_zero_stats<<<1, 64>>>();

    // 4: layer-1 merged GEMM (no CSR dependency) — lands in the profiled slot
    k_gemm2<128, false><<<GB, 256>>>(x, -1, W1l, W1r, b1, 0, 2);

    // 5-8: finish CSR
    k_scan1<<<SNB, 256>>>();
    k_scan2<<<1, 128>>>();
    k_scan3<<<SNB, 256>>>();
    k_scatter<<<EB, 256>>>(ei);

    // layer 1 aggregate + BN
    k_spmm_stats<<<SB, 256>>>(0, 2);
    k_finalize<<<1, 64>>>(g1, be1);

    // layer 2
    k_gemm2<64, true><<<GB, 256>>>(nullptr, 2, W2l, W2r, b2, 0, 1);
    k_spmm_stats<<<SB, 256>>>(0, 1);
    k_finalize<<<1, 64>>>(g2, be2);

    // layer 3
    k_gemm2<64, true><<<GB, 256>>>(nullptr, 1, W3l, W3r, b3, 0, 2);
    k_spmm_stats<<<SB, 256>>>(0, 2);
    k_finalize<<<1, 64>>>(g3, be3);

    // fusion (applies BN3 on the fly)
    k_fusion<<<FB, 256>>>(2, xgb, Wf1, bf1, Wf2, bf2, out);
}